// round 12
// baseline (speedup 1.0000x reference)
#include <cuda_runtime.h>
#include <cuda_fp16.h>
#include <cstdint>
#include <cstddef>

#define HWD  224
#define CIN  256
#define FOUT 256
#define OBS  14
#define KTOT 2304            // 9 taps * 256 c
#define NSTG 12              // 4 chunks * 3 stages; stage = 3 taps * 4 k16-steps

// smem layout (bytes)
#define WIN0   0             // two 16x16x64c fp16 windows (32 KB each)
#define BOFF   65536         // 3 cyclic B buffers, 48 KB each (3 taps x 16 KB)
#define BIASOF 212992        // 512 B
#define REDOF  213504        // mask-reduce scratch (64B sums + flag)
#define SMEM_TOTAL 213632

__device__ __align__(16) __half g_W2[256 * KTOT];   // [f][tap*256 + c]

__device__ __forceinline__ uint32_t smem_to_u32(const void* p) {
    uint32_t a;
    asm("{ .reg .u64 t; cvta.to.shared.u64 t, %1; cvt.u32.u64 %0, t; }" : "=r"(a) : "l"(p));
    return a;
}

#define LDSM4(r0, r1, r2, r3, addr) \
    asm volatile("ldmatrix.sync.aligned.m8n8.x4.shared.b16 {%0,%1,%2,%3}, [%4];" \
        : "=r"(r0), "=r"(r1), "=r"(r2), "=r"(r3) : "r"(addr))

#define MMA16816(d, a0, a1, a2, a3, b0, b1) \
    asm volatile("mma.sync.aligned.m16n8k16.row.col.f32.f16.f16.f32 " \
        "{%0,%1,%2,%3}, {%4,%5,%6,%7}, {%8,%9}, {%0,%1,%2,%3};" \
        : "+f"((d)[0]), "+f"((d)[1]), "+f"((d)[2]), "+f"((d)[3]) \
        : "r"(a0), "r"(a1), "r"(a2), "r"(a3), "r"(b0), "r"(b1))

#define CP_ASYNC16(dst, src) \
    asm volatile("cp.async.cg.shared.global [%0], [%1], 16;" \
        :: "r"((uint32_t)(dst)), "l"(src) : "memory")
#define CP_COMMIT() asm volatile("cp.async.commit_group;" ::: "memory")
#define CP_WAIT1()  asm volatile("cp.async.wait_group 1;" ::: "memory")

// ---------------------------------------------------------------------------
// Weight transpose to fp16: g_W2[f][k], k = tap*256 + c
// ---------------------------------------------------------------------------
__global__ void wprep_kernel(const float* __restrict__ wgt) {
    int idx = blockIdx.x * 256 + threadIdx.x;
    int f = idx & 255;
    int k = idx >> 8;
    g_W2[(size_t)f * KTOT + k] = __float2half_rn(wgt[(size_t)k * 256 + f]);
}

// ---------------------------------------------------------------------------
// Pipelined per-tap MMA compute: 4 k16-steps; NT m-tiles (compile-time).
// ---------------------------------------------------------------------------
template<int NT>
__device__ __forceinline__ void compute_tap(
    float acc[4][4][4],
    uint32_t winb, uint32_t btap,
    const uint32_t* __restrict__ arow, const uint32_t* __restrict__ ap7,
    const uint32_t* __restrict__ brow, const uint32_t* __restrict__ bp7,
    int acgl, int bg0)
{
    #pragma unroll
    for (int kk = 0; kk < 4; ++kk) {
        uint32_t bfr[2][4];
        int bcg = 2 * kk + bg0;
        #pragma unroll
        for (int u = 0; u < 2; ++u) {
            uint32_t ba = btap + brow[u] + (uint32_t)(((bcg ^ bp7[u])) << 4);
            LDSM4(bfr[u][0], bfr[u][1], bfr[u][2], bfr[u][3], ba);
        }
        int acg = 2 * kk + acgl;
        uint32_t a0, a1, a2, a3;
        {
            uint32_t aa = winb + arow[0] + (uint32_t)(((acg ^ ap7[0])) << 4);
            LDSM4(a0, a1, a2, a3, aa);
        }
        #pragma unroll
        for (int j = 0; j < NT; ++j) {
            uint32_t n0, n1, n2, n3;
            if (j + 1 < NT) {
                uint32_t aa = winb + arow[j + 1] + (uint32_t)(((acg ^ ap7[j + 1])) << 4);
                LDSM4(n0, n1, n2, n3, aa);
            }
            MMA16816(acc[j][0], a0, a1, a2, a3, bfr[0][0], bfr[0][1]);
            MMA16816(acc[j][1], a0, a1, a2, a3, bfr[0][2], bfr[0][3]);
            MMA16816(acc[j][2], a0, a1, a2, a3, bfr[1][0], bfr[1][1]);
            MMA16816(acc[j][3], a0, a1, a2, a3, bfr[1][2], bfr[1][3]);
            if (j + 1 < NT) { a0 = n0; a1 = n1; a2 = n2; a3 = n3; }
        }
    }
}

// ---------------------------------------------------------------------------
// Conv kernel: per (block, 128-filter half), 512 threads / 16 warps.
// Warps 0-11: MMA, wc=warp&3 (n32), wr=warp>>2 -> m-tiles {0-3,4-7,8-10}.
// Warps 12-15: HFMA2 scalar path, one per SMSP, rows 176-195 (5 each), all f.
// ---------------------------------------------------------------------------
__global__ void __launch_bounds__(512, 1)
conv_mma_kernel(const float* __restrict__ in, const float* __restrict__ mask,
                const float* __restrict__ bias, float* __restrict__ out) {
    int b = blockIdx.x;
    int fhalf = blockIdx.y;
    int nb = b >> 8, by = (b >> 4) & 15, bx = b & 15;
    int tid = threadIdx.x;
    int fbase = fhalf * 128;

    extern __shared__ char smem[];
    uint32_t sbase = smem_to_u32(smem);

    // ---- activity test (pooled mask mean > 0.5); threads 0-255 sample ----
    {
        double* sred = (double*)(smem + REDOF);
        int* sflag = (int*)(smem + REDOF + 64);
        if (tid < 256) {
            int ty = tid >> 4, tx = tid & 15;
            int h = by * OBS - 1 + ty;
            int w = bx * OBS - 1 + tx;
            float v = 0.f;
            if ((unsigned)h < HWD && (unsigned)w < HWD)
                v = mask[(nb * HWD + h) * HWD + w];
            double d = (double)v;
            #pragma unroll
            for (int o = 16; o > 0; o >>= 1)
                d += __shfl_down_sync(0xffffffffu, d, o);
            if ((tid & 31) == 0) sred[tid >> 5] = d;
        }
        __syncthreads();
        if (tid == 0) {
            double s = 0.0;
            #pragma unroll
            for (int i = 0; i < 8; ++i) s += sred[i];
            *sflag = (s * (1.0 / 256.0) > 0.5) ? 1 : 0;
        }
        __syncthreads();
        if (!*sflag) {
            if (tid < 196) {
                int Y = by * OBS + tid / OBS, X = bx * OBS + tid % OBS;
                float4* o = (float4*)(out + (((size_t)nb * HWD + Y) * HWD + X) * FOUT + fbase);
                float4 z = make_float4(0.f, 0.f, 0.f, 0.f);
                #pragma unroll
                for (int i = 0; i < 32; ++i) o[i] = z;
            }
            return;
        }
    }

    int warp = tid >> 5, lane = tid & 31;
    int is_mma = (warp < 12);
    int wc = warp & 3;
    int wr = warp >> 2;                       // 0..2 MMA row-groups; 3 = FFMA
    int mtb = wr * 4;                         // 0,4,8

    if (tid < 32) ((float4*)(smem + BIASOF))[tid] = ((const float4*)(bias + fbase))[tid];

    // MMA per-lane A-row table
    int P0[4];
    if (is_mma) {
        int mrow = (lane & 7) + ((lane >> 3) & 1) * 8;
        #pragma unroll
        for (int j = 0; j < 4; ++j) {
            int mt = mtb + j;
            if (mt > 10) mt = 10;
            int m = mt * 16 + mrow;
            if (m > 175) m = 175;
            int py = m / 14, px = m - py * 14;
            P0[j] = (py + 1) * 16 + (px + 1);
        }
    }
    int acgl = (lane >> 4) & 1;
    int bnl  = ((lane >> 4) & 1) * 8 + (lane & 7);
    int bg0  = (lane >> 3) & 1;

    uint32_t brow[2], bp7[2];
    #pragma unroll
    for (int u = 0; u < 2; ++u) {
        int bn = wc * 32 + u * 16 + bnl;
        brow[u] = (uint32_t)bn * 128;
        bp7[u]  = (uint32_t)(bn & 7);
    }

    float acc[4][4][4];
    #pragma unroll
    for (int j = 0; j < 4; ++j)
        #pragma unroll
        for (int t = 0; t < 4; ++t)
            #pragma unroll
            for (int e = 0; e < 4; ++e) acc[j][t][e] = 0.f;

    // FFMA warp state: rows r0..r0+4, filters f0..f0+3
    int r0 = 176 + (warp - 12) * 5;
    int f0 = lane * 4;
    __half2 hz = __float2half2_rn(0.f);
    __half2 hacc[5][4];
    float facc[5][4];
    #pragma unroll
    for (int i = 0; i < 5; ++i)
        #pragma unroll
        for (int f = 0; f < 4; ++f) { hacc[i][f] = hz; facc[i][f] = 0.f; }
    uint32_t wrowf[4], wp7f[4];
    #pragma unroll
    for (int f = 0; f < 4; ++f) {
        int n = f0 + f;
        wrowf[f] = (uint32_t)n * 128;
        wp7f[f]  = (uint32_t)(n & 7);
    }

    const float* inb = in + (size_t)nb * HWD * HWD * CIN;
    int h0 = by * OBS - 1;
    int w0 = bx * OBS - 1;

    auto load_window = [&](int cc, int wb) {
        int c0 = cc * 64;
        char* wdst = smem + WIN0 + wb * 32768;
        #pragma unroll
        for (int j = 0; j < 4; ++j) {
            int u = tid + j * 512;
            int p = u >> 3, g = u & 7;
            int y = p >> 4, x = p & 15;
            int gy = h0 + y, gx = w0 + x;
            float v[8];
            #pragma unroll
            for (int e = 0; e < 8; ++e) v[e] = 0.f;
            if ((unsigned)gy < HWD && (unsigned)gx < HWD) {
                const float* sp = inb + (((size_t)gy * HWD + gx) * CIN) + c0 + g * 8;
                float4 va = ((const float4*)sp)[0];
                float4 vb = ((const float4*)sp)[1];
                v[0] = va.x; v[1] = va.y; v[2] = va.z; v[3] = va.w;
                v[4] = vb.x; v[5] = vb.y; v[6] = vb.z; v[7] = vb.w;
            }
            union { __half hf[8]; uint4 u4; } H;
            #pragma unroll
            for (int e = 0; e < 8; ++e) H.hf[e] = __float2half_rn(v[e]);
            *(uint4*)(wdst + p * 128 + (((g ^ (p & 7))) << 4)) = H.u4;
        }
    };

    auto issue_B = [&](int t) {
        int cct = t / 3, tbt = (t % 3) * 3;
        uint32_t bufb = sbase + BOFF + (uint32_t)(t % 3) * 49152;
        const __half* wsrc = g_W2 + tbt * 256 + cct * 64;
        #pragma unroll
        for (int j = 0; j < 6; ++j) {
            int u = tid + j * 512;
            int tl = u >> 10;
            int rem = u & 1023;
            int n = rem >> 3, g = rem & 7;
            const __half* src = wsrc + (size_t)(fbase + n) * KTOT + tl * 256 + g * 8;
            uint32_t dst = bufb + tl * 16384 + n * 128 + (((g ^ (n & 7))) << 4);
            CP_ASYNC16(dst, src);
        }
    };

    issue_B(0);
    CP_COMMIT();
    load_window(0, 0);

    for (int s = 0; s < NSTG; ++s) {
        int cc = s / 3;
        int tb = (s % 3) * 3;

        if (s + 1 < NSTG) issue_B(s + 1);
        CP_COMMIT();
        CP_WAIT1();
        __syncthreads();

        if ((s % 3) == 2 && cc + 1 < 4) load_window(cc + 1, (cc + 1) & 1);

        uint32_t winb = sbase + WIN0 + (uint32_t)(cc & 1) * 32768;
        uint32_t bbuf = sbase + BOFF + (uint32_t)(s % 3) * 49152;
        char* winp = smem + WIN0 + (cc & 1) * 32768;
        char* bbp  = smem + BOFF + (s % 3) * 49152;

        if (is_mma) {
            #pragma unroll
            for (int tl = 0; tl < 3; ++tl) {
                int tap = tb + tl;
                int dy = tap / 3 - 1, dx = tap - (tap / 3) * 3 - 1;
                int doff = dy * 16 + dx;
                uint32_t btap = bbuf + tl * 16384;

                uint32_t arow[4], ap7[4];
                #pragma unroll
                for (int j = 0; j < 4; ++j) {
                    int P = P0[j] + doff;
                    arow[j] = (uint32_t)P * 128;
                    ap7[j]  = (uint32_t)(P & 7);
                }
                if (wr < 2)
                    compute_tap<4>(acc, winb, btap, arow, ap7, brow, bp7, acgl, bg0);
                else
                    compute_tap<3>(acc, winb, btap, arow, ap7, brow, bp7, acgl, bg0);
            }
        } else {
            // ---- HFMA2 path: rows r0..r0+4, filters f0..f0+3, 3 taps ----
            #pragma unroll
            for (int tl = 0; tl < 3; ++tl) {
                int tap = tb + tl;
                int dy = tap / 3 - 1, dx = tap - (tap / 3) * 3 - 1;
                int doff = dy * 16 + dx;
                char* btp = bbp + tl * 16384;

                uint32_t arow[5], ap7[5];
                #pragma unroll
                for (int i = 0; i < 5; ++i) {
                    int row = r0 + i;
                    int py = row / 14, px = row - py * 14;
                    int P = (py + 1) * 16 + (px + 1) + doff;
                    arow[i] = (uint32_t)P * 128;
                    ap7[i]  = (uint32_t)(P & 7);
                }
                #pragma unroll
                for (int g = 0; g < 8; ++g) {
                    union { uint4 u4; __half2 h2[4]; } a4[5], w4[4];
                    #pragma unroll
                    for (int i = 0; i < 5; ++i)
                        a4[i].u4 = *(const uint4*)(winp + arow[i] + (((g ^ ap7[i])) << 4));
                    #pragma unroll
                    for (int f = 0; f < 4; ++f)
                        w4[f].u4 = *(const uint4*)(btp + wrowf[f] + (((g ^ wp7f[f])) << 4));
                    #pragma unroll
                    for (int i = 0; i < 5; ++i)
                        #pragma unroll
                        for (int f = 0; f < 4; ++f) {
                            __half2 hsum = hacc[i][f];
                            hsum = __hfma2(a4[i].h2[0], w4[f].h2[0], hsum);
                            hsum = __hfma2(a4[i].h2[1], w4[f].h2[1], hsum);
                            hsum = __hfma2(a4[i].h2[2], w4[f].h2[2], hsum);
                            hsum = __hfma2(a4[i].h2[3], w4[f].h2[3], hsum);
                            hacc[i][f] = hsum;
                        }
                }
                // flush fp16 partials (64 k) into fp32
                #pragma unroll
                for (int i = 0; i < 5; ++i)
                    #pragma unroll
                    for (int f = 0; f < 4; ++f) {
                        float2 t2 = __half22float2(hacc[i][f]);
                        facc[i][f] += t2.x + t2.y;
                        hacc[i][f] = hz;
                    }
            }
        }
    }

    // ---- epilogue: bias + relu + store ----
    const float* sb = (const float*)(smem + BIASOF);
    if (is_mma) {
        int NTe = (wr < 2) ? 4 : 3;
        #pragma unroll
        for (int j = 0; j < 4; ++j) {
            if (j < NTe) {
                int mt = mtb + j;
                #pragma unroll
                for (int u = 0; u < 2; ++u) {
                    #pragma unroll
                    for (int hf = 0; hf < 2; ++hf) {
                        int nn = wc * 32 + u * 16 + hf * 8 + (lane & 3) * 2;
                        float bz0 = sb[nn], bz1 = sb[nn + 1];
                        #pragma unroll
                        for (int h2 = 0; h2 < 2; ++h2) {
                            int m = mt * 16 + (lane >> 2) + h2 * 8;
                            if (m < 176) {
                                int py = m / 14, px = m - py * 14;
                                float* o = out + (((size_t)nb * HWD + by * OBS + py) * HWD
                                                  + bx * OBS + px) * FOUT + fbase + nn;
                                float2 v;
                                v.x = fmaxf(acc[j][u * 2 + hf][h2 * 2 + 0] + bz0, 0.f);
                                v.y = fmaxf(acc[j][u * 2 + hf][h2 * 2 + 1] + bz1, 0.f);
                                *(float2*)o = v;
                            }
                        }
                    }
                }
            }
        }
    } else {
        float b0 = sb[f0], b1 = sb[f0 + 1], b2 = sb[f0 + 2], b3 = sb[f0 + 3];
        #pragma unroll
        for (int i = 0; i < 5; ++i) {
            int row = r0 + i;
            int py = row / 14, px = row - py * 14;
            float* o = out + (((size_t)nb * HWD + by * OBS + py) * HWD
                              + bx * OBS + px) * FOUT + fbase + f0;
            float4 v;
            v.x = fmaxf(facc[i][0] + b0, 0.f);
            v.y = fmaxf(facc[i][1] + b1, 0.f);
            v.z = fmaxf(facc[i][2] + b2, 0.f);
            v.w = fmaxf(facc[i][3] + b3, 0.f);
            *(float4*)o = v;
        }
    }
}

extern "C" void kernel_launch(void* const* d_in, const int* in_sizes, int n_in,
                              void* d_out, int out_size) {
    (void)in_sizes; (void)n_in; (void)out_size;
    const float* in   = (const float*)d_in[0];   // (4,224,224,256)
    const float* mask = (const float*)d_in[1];   // (4,224,224,1)
    const float* wgt  = (const float*)d_in[2];   // (3,3,256,256)
    const float* bias = (const float*)d_in[3];   // (256,)
    float* out = (float*)d_out;

    cudaFuncSetAttribute(conv_mma_kernel,
                         cudaFuncAttributeMaxDynamicSharedMemorySize, SMEM_TOTAL);
    wprep_kernel<<<2304, 256>>>(wgt);
    dim3 grid(1024, 2);
    conv_mma_kernel<<<grid, 512, SMEM_TOTAL>>>(in, mask, bias, out);
}

// round 13
// speedup vs baseline: 1.3184x; 1.3184x over previous
#include <cuda_runtime.h>
#include <cuda_fp16.h>
#include <cstdint>
#include <cstddef>

#define HWD  224
#define CIN  256
#define FOUT 256
#define OBS  14
#define KTOT 2304            // 9 taps * 256 c
#define NSTG 12              // 4 chunks * 3 stages; stage = 3 taps * 4 k16-steps

// smem layout (bytes)
#define WIN0   0             // two 16x16x64c fp16 windows (32 KB each)
#define BOFF   65536         // 3 cyclic B buffers, 48 KB each (3 taps x 16 KB)
#define BIASOF 212992        // 512 B
#define REDOF  213504        // mask-reduce scratch (64B sums + flag)
#define SMEM_TOTAL 213632

__device__ __align__(16) __half g_W2[256 * KTOT];   // [f][tap*256 + c]

__device__ __forceinline__ uint32_t smem_to_u32(const void* p) {
    uint32_t a;
    asm("{ .reg .u64 t; cvta.to.shared.u64 t, %1; cvt.u32.u64 %0, t; }" : "=r"(a) : "l"(p));
    return a;
}

#define LDSM4(r0, r1, r2, r3, addr) \
    asm volatile("ldmatrix.sync.aligned.m8n8.x4.shared.b16 {%0,%1,%2,%3}, [%4];" \
        : "=r"(r0), "=r"(r1), "=r"(r2), "=r"(r3) : "r"(addr))

// f16-accumulator MMA: D,C are 2 b32 regs (4 halves)
#define MMA16816H(d0, d1, a0, a1, a2, a3, b0, b1) \
    asm volatile("mma.sync.aligned.m16n8k16.row.col.f16.f16.f16.f16 " \
        "{%0,%1}, {%2,%3,%4,%5}, {%6,%7}, {%0,%1};" \
        : "+r"(d0), "+r"(d1) \
        : "r"(a0), "r"(a1), "r"(a2), "r"(a3), "r"(b0), "r"(b1))

#define CP_ASYNC16(dst, src) \
    asm volatile("cp.async.cg.shared.global [%0], [%1], 16;" \
        :: "r"((uint32_t)(dst)), "l"(src) : "memory")
#define CP_COMMIT() asm volatile("cp.async.commit_group;" ::: "memory")
#define CP_WAIT1()  asm volatile("cp.async.wait_group 1;" ::: "memory")

// ---------------------------------------------------------------------------
// Weight transpose to fp16: g_W2[f][k], k = tap*256 + c
// ---------------------------------------------------------------------------
__global__ void wprep_kernel(const float* __restrict__ wgt) {
    int idx = blockIdx.x * 256 + threadIdx.x;
    int f = idx & 255;
    int k = idx >> 8;
    g_W2[(size_t)f * KTOT + k] = __float2half_rn(wgt[(size_t)k * 256 + f]);
}

// ---------------------------------------------------------------------------
// Per-tap compute, f16 accumulator chain over the 4 k16-steps, then a single
// fp32 flush. NT m-tiles (compile-time 4 or 3).
// ---------------------------------------------------------------------------
template<int NT>
__device__ __forceinline__ void compute_tap(
    float acc[4][4][4],
    uint32_t winb, uint32_t btap,
    const uint32_t* __restrict__ arow, const uint32_t* __restrict__ ap7,
    const uint32_t* __restrict__ brow, const uint32_t* __restrict__ bp7,
    int acgl, int bg0)
{
    uint32_t ch[NT][4][2];
    #pragma unroll
    for (int j = 0; j < NT; ++j)
        #pragma unroll
        for (int t = 0; t < 4; ++t) { ch[j][t][0] = 0u; ch[j][t][1] = 0u; }

    #pragma unroll
    for (int kk = 0; kk < 4; ++kk) {
        uint32_t bfr[2][4];
        int bcg = 2 * kk + bg0;
        #pragma unroll
        for (int u = 0; u < 2; ++u) {
            uint32_t ba = btap + brow[u] + (uint32_t)(((bcg ^ bp7[u])) << 4);
            LDSM4(bfr[u][0], bfr[u][1], bfr[u][2], bfr[u][3], ba);
        }
        int acg = 2 * kk + acgl;
        uint32_t a0, a1, a2, a3;
        {
            uint32_t aa = winb + arow[0] + (uint32_t)(((acg ^ ap7[0])) << 4);
            LDSM4(a0, a1, a2, a3, aa);
        }
        #pragma unroll
        for (int j = 0; j < NT; ++j) {
            uint32_t n0, n1, n2, n3;
            if (j + 1 < NT) {
                uint32_t aa = winb + arow[j + 1] + (uint32_t)(((acg ^ ap7[j + 1])) << 4);
                LDSM4(n0, n1, n2, n3, aa);
            }
            MMA16816H(ch[j][0][0], ch[j][0][1], a0, a1, a2, a3, bfr[0][0], bfr[0][1]);
            MMA16816H(ch[j][1][0], ch[j][1][1], a0, a1, a2, a3, bfr[0][2], bfr[0][3]);
            MMA16816H(ch[j][2][0], ch[j][2][1], a0, a1, a2, a3, bfr[1][0], bfr[1][1]);
            MMA16816H(ch[j][3][0], ch[j][3][1], a0, a1, a2, a3, bfr[1][2], bfr[1][3]);
            if (j + 1 < NT) { a0 = n0; a1 = n1; a2 = n2; a3 = n3; }
        }
    }

    // flush f16 chains into fp32 accumulators
    #pragma unroll
    for (int j = 0; j < NT; ++j)
        #pragma unroll
        for (int t = 0; t < 4; ++t) {
            float2 lo = __half22float2(*(__half2*)&ch[j][t][0]);
            float2 hi = __half22float2(*(__half2*)&ch[j][t][1]);
            acc[j][t][0] += lo.x;
            acc[j][t][1] += lo.y;
            acc[j][t][2] += hi.x;
            acc[j][t][3] += hi.y;
        }
}

// ---------------------------------------------------------------------------
// Conv kernel: per (block, 128-filter half), 512 threads / 16 warps.
// wc = warp&3 (n32) => SMSP carries 4/3/3/3 m-groups = 13 tiles, balanced.
// wr = warp>>2: m-tile bases {0,4,7,10}, sizes {4,3,3,3}.
// ---------------------------------------------------------------------------
__global__ void __launch_bounds__(512, 1)
conv_mma_kernel(const float* __restrict__ in, const float* __restrict__ mask,
                const float* __restrict__ bias, float* __restrict__ out) {
    int b = blockIdx.x;
    int fhalf = blockIdx.y;
    int nb = b >> 8, by = (b >> 4) & 15, bx = b & 15;
    int tid = threadIdx.x;
    int fbase = fhalf * 128;

    extern __shared__ char smem[];
    uint32_t sbase = smem_to_u32(smem);

    // ---- activity test (pooled mask mean > 0.5); threads 0-255 sample ----
    {
        double* sred = (double*)(smem + REDOF);
        int* sflag = (int*)(smem + REDOF + 64);
        if (tid < 256) {
            int ty = tid >> 4, tx = tid & 15;
            int h = by * OBS - 1 + ty;
            int w = bx * OBS - 1 + tx;
            float v = 0.f;
            if ((unsigned)h < HWD && (unsigned)w < HWD)
                v = mask[(nb * HWD + h) * HWD + w];
            double d = (double)v;
            #pragma unroll
            for (int o = 16; o > 0; o >>= 1)
                d += __shfl_down_sync(0xffffffffu, d, o);
            if ((tid & 31) == 0) sred[tid >> 5] = d;
        }
        __syncthreads();
        if (tid == 0) {
            double s = 0.0;
            #pragma unroll
            for (int i = 0; i < 8; ++i) s += sred[i];
            *sflag = (s * (1.0 / 256.0) > 0.5) ? 1 : 0;
        }
        __syncthreads();
        if (!*sflag) {
            if (tid < 196) {
                int Y = by * OBS + tid / OBS, X = bx * OBS + tid % OBS;
                float4* o = (float4*)(out + (((size_t)nb * HWD + Y) * HWD + X) * FOUT + fbase);
                float4 z = make_float4(0.f, 0.f, 0.f, 0.f);
                #pragma unroll
                for (int i = 0; i < 32; ++i) o[i] = z;
            }
            return;
        }
    }

    int warp = tid >> 5, lane = tid & 31;
    int wc = warp & 3;            // n column-group (n32), = SMSP id
    int wr = warp >> 2;           // m row-group
    int mtb = (wr == 0) ? 0 : (3 * wr + 1);   // 0,4,7,10

    if (tid < 32) ((float4*)(smem + BIASOF))[tid] = ((const float4*)(bias + fbase))[tid];

    // per-lane A-row table (window pixel index per m-tile, pre-halo)
    int P0[4];
    {
        int mrow = (lane & 7) + ((lane >> 3) & 1) * 8;
        #pragma unroll
        for (int j = 0; j < 4; ++j) {
            int mt = mtb + j;
            if (mt > 12) mt = 12;
            int m = mt * 16 + mrow;
            if (m > 195) m = 195;
            int py = m / 14, px = m - py * 14;
            P0[j] = (py + 1) * 16 + (px + 1);
        }
    }
    int acgl = (lane >> 4) & 1;
    int bnl  = ((lane >> 4) & 1) * 8 + (lane & 7);
    int bg0  = (lane >> 3) & 1;

    uint32_t brow[2], bp7[2];
    #pragma unroll
    for (int u = 0; u < 2; ++u) {
        int bn = wc * 32 + u * 16 + bnl;
        brow[u] = (uint32_t)bn * 128;
        bp7[u]  = (uint32_t)(bn & 7);
    }

    float acc[4][4][4];
    #pragma unroll
    for (int j = 0; j < 4; ++j)
        #pragma unroll
        for (int t = 0; t < 4; ++t)
            #pragma unroll
            for (int e = 0; e < 4; ++e) acc[j][t][e] = 0.f;

    const float* inb = in + (size_t)nb * HWD * HWD * CIN;
    int h0 = by * OBS - 1;
    int w0 = bx * OBS - 1;

    // window loader: 2048 uint4 units over 512 threads (4 each)
    auto load_window = [&](int cc, int wb) {
        int c0 = cc * 64;
        char* wdst = smem + WIN0 + wb * 32768;
        #pragma unroll
        for (int j = 0; j < 4; ++j) {
            int u = tid + j * 512;
            int p = u >> 3, g = u & 7;
            int y = p >> 4, x = p & 15;
            int gy = h0 + y, gx = w0 + x;
            float v[8];
            #pragma unroll
            for (int e = 0; e < 8; ++e) v[e] = 0.f;
            if ((unsigned)gy < HWD && (unsigned)gx < HWD) {
                const float* sp = inb + (((size_t)gy * HWD + gx) * CIN) + c0 + g * 8;
                float4 va = ((const float4*)sp)[0];
                float4 vb = ((const float4*)sp)[1];
                v[0] = va.x; v[1] = va.y; v[2] = va.z; v[3] = va.w;
                v[4] = vb.x; v[5] = vb.y; v[6] = vb.z; v[7] = vb.w;
            }
            union { __half hf[8]; uint4 u4; } H;
            #pragma unroll
            for (int e = 0; e < 8; ++e) H.hf[e] = __float2half_rn(v[e]);
            *(uint4*)(wdst + p * 128 + (((g ^ (p & 7))) << 4)) = H.u4;
        }
    };

    // B stage issuer: 3072 x 16B over 512 threads (6 cp.async each)
    auto issue_B = [&](int t) {
        int cct = t / 3, tbt = (t % 3) * 3;
        uint32_t bufb = sbase + BOFF + (uint32_t)(t % 3) * 49152;
        const __half* wsrc = g_W2 + tbt * 256 + cct * 64;
        #pragma unroll
        for (int j = 0; j < 6; ++j) {
            int u = tid + j * 512;
            int tl = u >> 10;
            int rem = u & 1023;
            int n = rem >> 3, g = rem & 7;
            const __half* src = wsrc + (size_t)(fbase + n) * KTOT + tl * 256 + g * 8;
            uint32_t dst = bufb + tl * 16384 + n * 128 + (((g ^ (n & 7))) << 4);
            CP_ASYNC16(dst, src);
        }
    };

    // prologue: B(0) in flight, window chunk 0 into winbuf 0
    issue_B(0);
    CP_COMMIT();
    load_window(0, 0);

    for (int s = 0; s < NSTG; ++s) {
        int cc = s / 3;
        int tb = (s % 3) * 3;

        if (s + 1 < NSTG) issue_B(s + 1);
        CP_COMMIT();
        CP_WAIT1();            // B(s) complete locally
        __syncthreads();       // publish B(s) + window/bias STS; compute(s-1) done

        // prefetch next chunk's window into the other winbuf
        if ((s % 3) == 2 && cc + 1 < 4) load_window(cc + 1, (cc + 1) & 1);

        uint32_t winb = sbase + WIN0 + (uint32_t)(cc & 1) * 32768;
        uint32_t bbuf = sbase + BOFF + (uint32_t)(s % 3) * 49152;

        #pragma unroll
        for (int tl = 0; tl < 3; ++tl) {
            int tap = tb + tl;
            int dy = tap / 3 - 1, dx = tap - (tap / 3) * 3 - 1;
            int doff = dy * 16 + dx;
            uint32_t btap = bbuf + tl * 16384;

            uint32_t arow[4], ap7[4];
            #pragma unroll
            for (int j = 0; j < 4; ++j) {
                int P = P0[j] + doff;
                arow[j] = (uint32_t)P * 128;
                ap7[j]  = (uint32_t)(P & 7);
            }
            if (wr == 0)
                compute_tap<4>(acc, winb, btap, arow, ap7, brow, bp7, acgl, bg0);
            else
                compute_tap<3>(acc, winb, btap, arow, ap7, brow, bp7, acgl, bg0);
        }
    }

    // ---- epilogue: bias + relu + store ----
    const float* sb = (const float*)(smem + BIASOF);
    int NTe = (wr == 0) ? 4 : 3;
    #pragma unroll
    for (int j = 0; j < 4; ++j) {
        if (j < NTe) {
            int mt = mtb + j;
            #pragma unroll
            for (int u = 0; u < 2; ++u) {
                #pragma unroll
                for (int hf = 0; hf < 2; ++hf) {
                    int nn = wc * 32 + u * 16 + hf * 8 + (lane & 3) * 2;
                    float bz0 = sb[nn], bz1 = sb[nn + 1];
                    #pragma unroll
                    for (int h2 = 0; h2 < 2; ++h2) {
                        int m = mt * 16 + (lane >> 2) + h2 * 8;
                        if (m < 196) {
                            int py = m / 14, px = m - py * 14;
                            float* o = out + (((size_t)nb * HWD + by * OBS + py) * HWD
                                              + bx * OBS + px) * FOUT + fbase + nn;
                            float2 v;
                            v.x = fmaxf(acc[j][u * 2 + hf][h2 * 2 + 0] + bz0, 0.f);
                            v.y = fmaxf(acc[j][u * 2 + hf][h2 * 2 + 1] + bz1, 0.f);
                            *(float2*)o = v;
                        }
                    }
                }
            }
        }
    }
}

extern "C" void kernel_launch(void* const* d_in, const int* in_sizes, int n_in,
                              void* d_out, int out_size) {
    (void)in_sizes; (void)n_in; (void)out_size;
    const float* in   = (const float*)d_in[0];   // (4,224,224,256)
    const float* mask = (const float*)d_in[1];   // (4,224,224,1)
    const float* wgt  = (const float*)d_in[2];   // (3,3,256,256)
    const float* bias = (const float*)d_in[3];   // (256,)
    float* out = (float*)d_out;

    cudaFuncSetAttribute(conv_mma_kernel,
                         cudaFuncAttributeMaxDynamicSharedMemorySize, SMEM_TOTAL);
    wprep_kernel<<<2304, 256>>>(wgt);
    dim3 grid(1024, 2);
    conv_mma_kernel<<<grid, 512, SMEM_TOTAL>>>(in, mask, bias, out);
}

// round 15
// speedup vs baseline: 1.9893x; 1.5089x over previous
#include <cuda_runtime.h>
#include <cuda_fp16.h>
#include <cstdint>
#include <cstddef>

#define HWD  224
#define CIN  256
#define FOUT 256
#define OBS  14
#define KTOT 2304            // 9 taps * 256 c
#define NSTG 36              // 4 chunks * 9 taps; stage = 1 tap * 4 k16-steps

// smem layout (bytes)
#define WIN0   0             // two 16x16x64c fp16 windows (32 KB each)
#define BOFF   65536         // 3 cyclic B buffers, 8 KB each (64f x 128B)
#define BIASOF 90112         // 256 B (64 floats)
#define REDOF  90368         // mask-reduce scratch (64B sums + flag)
#define SMEM_TOTAL 90496

__device__ __align__(16) __half g_W2[256 * KTOT];   // [f][tap*256 + c]

__device__ __forceinline__ uint32_t smem_to_u32(const void* p) {
    uint32_t a;
    asm("{ .reg .u64 t; cvta.to.shared.u64 t, %1; cvt.u32.u64 %0, t; }" : "=r"(a) : "l"(p));
    return a;
}

#define LDSM4(r0, r1, r2, r3, addr) \
    asm volatile("ldmatrix.sync.aligned.m8n8.x4.shared.b16 {%0,%1,%2,%3}, [%4];" \
        : "=r"(r0), "=r"(r1), "=r"(r2), "=r"(r3) : "r"(addr))

#define MMA16816(d, a0, a1, a2, a3, b0, b1) \
    asm volatile("mma.sync.aligned.m16n8k16.row.col.f32.f16.f16.f32 " \
        "{%0,%1,%2,%3}, {%4,%5,%6,%7}, {%8,%9}, {%0,%1,%2,%3};" \
        : "+f"((d)[0]), "+f"((d)[1]), "+f"((d)[2]), "+f"((d)[3]) \
        : "r"(a0), "r"(a1), "r"(a2), "r"(a3), "r"(b0), "r"(b1))

#define CP_ASYNC16(dst, src) \
    asm volatile("cp.async.cg.shared.global [%0], [%1], 16;" \
        :: "r"((uint32_t)(dst)), "l"(src) : "memory")
#define CP_COMMIT() asm volatile("cp.async.commit_group;" ::: "memory")
#define CP_WAIT1()  asm volatile("cp.async.wait_group 1;" ::: "memory")

// ---------------------------------------------------------------------------
// Weight transpose to fp16: g_W2[f][k], k = tap*256 + c
// ---------------------------------------------------------------------------
__global__ void wprep_kernel(const float* __restrict__ wgt) {
    int idx = blockIdx.x * 256 + threadIdx.x;
    int f = idx & 255;
    int k = idx >> 8;
    g_W2[(size_t)f * KTOT + k] = __float2half_rn(wgt[(size_t)k * 256 + f]);
}

// ---------------------------------------------------------------------------
// Pipelined per-tap MMA compute: 4 k16-steps; NT m-tiles (compile-time).
// fp32 accumulators (reverted from f16 chains).
// ---------------------------------------------------------------------------
template<int NT>
__device__ __forceinline__ void compute_tap(
    float acc[4][4][4],
    uint32_t winb, uint32_t btap,
    const uint32_t* __restrict__ arow, const uint32_t* __restrict__ ap7,
    const uint32_t* __restrict__ brow, const uint32_t* __restrict__ bp7,
    int acgl, int bg0)
{
    #pragma unroll
    for (int kk = 0; kk < 4; ++kk) {
        uint32_t bfr[2][4];
        int bcg = 2 * kk + bg0;
        #pragma unroll
        for (int u = 0; u < 2; ++u) {
            uint32_t ba = btap + brow[u] + (uint32_t)(((bcg ^ bp7[u])) << 4);
            LDSM4(bfr[u][0], bfr[u][1], bfr[u][2], bfr[u][3], ba);
        }
        int acg = 2 * kk + acgl;
        uint32_t a0, a1, a2, a3;
        {
            uint32_t aa = winb + arow[0] + (uint32_t)(((acg ^ ap7[0])) << 4);
            LDSM4(a0, a1, a2, a3, aa);
        }
        #pragma unroll
        for (int j = 0; j < NT; ++j) {
            uint32_t n0, n1, n2, n3;
            if (j + 1 < NT) {
                uint32_t aa = winb + arow[j + 1] + (uint32_t)(((acg ^ ap7[j + 1])) << 4);
                LDSM4(n0, n1, n2, n3, aa);
            }
            MMA16816(acc[j][0], a0, a1, a2, a3, bfr[0][0], bfr[0][1]);
            MMA16816(acc[j][1], a0, a1, a2, a3, bfr[0][2], bfr[0][3]);
            MMA16816(acc[j][2], a0, a1, a2, a3, bfr[1][0], bfr[1][1]);
            MMA16816(acc[j][3], a0, a1, a2, a3, bfr[1][2], bfr[1][3]);
            if (j + 1 < NT) { a0 = n0; a1 = n1; a2 = n2; a3 = n3; }
        }
    }
}

// ---------------------------------------------------------------------------
// Conv kernel: per (block, 64-filter quarter), 256 threads / 8 warps,
// 2 CTAs per SM (reg-exact: 256 x 128 x 2 = 64K regs).
// wc = warp&1 (n32), wr = warp>>1 (m-tile bases {0,4,7,10}, sizes {4,3,3,3}).
// blockIdx.x = filter quarter (fast) so sibling CTAs share window via L2.
// ---------------------------------------------------------------------------
__global__ void __launch_bounds__(256, 2)
conv_mma_kernel(const float* __restrict__ in, const float* __restrict__ mask,
                const float* __restrict__ bias, float* __restrict__ out) {
    int fquart = blockIdx.x;          // 0..3
    int b = blockIdx.y;               // 0..1023
    int nb = b >> 8, by = (b >> 4) & 15, bx = b & 15;
    int tid = threadIdx.x;
    int fbase = fquart * 64;

    extern __shared__ char smem[];
    uint32_t sbase = smem_to_u32(smem);

    // ---- activity test (pooled mask mean > 0.5) ----
    {
        double* sred = (double*)(smem + REDOF);
        int* sflag = (int*)(smem + REDOF + 64);
        int ty = tid >> 4, tx = tid & 15;
        int h = by * OBS - 1 + ty;
        int w = bx * OBS - 1 + tx;
        float v = 0.f;
        if ((unsigned)h < HWD && (unsigned)w < HWD)
            v = mask[(nb * HWD + h) * HWD + w];
        double d = (double)v;
        #pragma unroll
        for (int o = 16; o > 0; o >>= 1)
            d += __shfl_down_sync(0xffffffffu, d, o);
        if ((tid & 31) == 0) sred[tid >> 5] = d;
        __syncthreads();
        if (tid == 0) {
            double s = 0.0;
            #pragma unroll
            for (int i = 0; i < 8; ++i) s += sred[i];
            *sflag = (s * (1.0 / 256.0) > 0.5) ? 1 : 0;
        }
        __syncthreads();
        if (!*sflag) {
            if (tid < 196) {
                int Y = by * OBS + tid / OBS, X = bx * OBS + tid % OBS;
                float4* o = (float4*)(out + (((size_t)nb * HWD + Y) * HWD + X) * FOUT + fbase);
                float4 z = make_float4(0.f, 0.f, 0.f, 0.f);
                #pragma unroll
                for (int i = 0; i < 16; ++i) o[i] = z;
            }
            return;
        }
    }

    int warp = tid >> 5, lane = tid & 31;
    int wc = warp & 1;            // n column-group (n32)
    int wr = warp >> 1;           // m row-group 0..3
    int mtb = (wr == 0) ? 0 : (3 * wr + 1);   // 0,4,7,10

    if (tid < 16) ((float4*)(smem + BIASOF))[tid] = ((const float4*)(bias + fbase))[tid];

    // per-lane A-row table (window pixel index per m-tile, pre-halo)
    int P0[4];
    {
        int mrow = (lane & 7) + ((lane >> 3) & 1) * 8;
        #pragma unroll
        for (int j = 0; j < 4; ++j) {
            int mt = mtb + j;
            if (mt > 12) mt = 12;
            int m = mt * 16 + mrow;
            if (m > 195) m = 195;
            int py = m / 14, px = m - py * 14;
            P0[j] = (py + 1) * 16 + (px + 1);
        }
    }
    int acgl = (lane >> 4) & 1;
    int bnl  = ((lane >> 4) & 1) * 8 + (lane & 7);
    int bg0  = (lane >> 3) & 1;

    uint32_t brow[2], bp7[2];
    #pragma unroll
    for (int u = 0; u < 2; ++u) {
        int bn = wc * 32 + u * 16 + bnl;       // < 64
        brow[u] = (uint32_t)bn * 128;
        bp7[u]  = (uint32_t)(bn & 7);
    }

    float acc[4][4][4];
    #pragma unroll
    for (int j = 0; j < 4; ++j)
        #pragma unroll
        for (int t = 0; t < 4; ++t)
            #pragma unroll
            for (int e = 0; e < 4; ++e) acc[j][t][e] = 0.f;

    const float* inb = in + (size_t)nb * HWD * HWD * CIN;
    int h0 = by * OBS - 1;
    int w0 = bx * OBS - 1;

    // window loader: 2048 uint4 units over 256 threads (8 each)
    auto load_window = [&](int cc, int wb) {
        int c0 = cc * 64;
        char* wdst = smem + WIN0 + wb * 32768;
        #pragma unroll
        for (int j = 0; j < 8; ++j) {
            int u = tid + j * 256;
            int p = u >> 3, g = u & 7;
            int y = p >> 4, x = p & 15;
            int gy = h0 + y, gx = w0 + x;
            float v[8];
            #pragma unroll
            for (int e = 0; e < 8; ++e) v[e] = 0.f;
            if ((unsigned)gy < HWD && (unsigned)gx < HWD) {
                const float* sp = inb + (((size_t)gy * HWD + gx) * CIN) + c0 + g * 8;
                float4 va = ((const float4*)sp)[0];
                float4 vb = ((const float4*)sp)[1];
                v[0] = va.x; v[1] = va.y; v[2] = va.z; v[3] = va.w;
                v[4] = vb.x; v[5] = vb.y; v[6] = vb.z; v[7] = vb.w;
            }
            union { __half hf[8]; uint4 u4; } H;
            #pragma unroll
            for (int e = 0; e < 8; ++e) H.hf[e] = __float2half_rn(v[e]);
            *(uint4*)(wdst + p * 128 + (((g ^ (p & 7))) << 4)) = H.u4;
        }
    };

    // B stage issuer: 1 tap = 64 rows x 128B = 512 uint4 over 256 threads
    auto issue_B = [&](int t) {
        int cct = t / 9, tapt = t - cct * 9;
        uint32_t bufb = sbase + BOFF + (uint32_t)(t % 3) * 8192;
        const __half* wsrc = g_W2 + tapt * 256 + cct * 64;
        #pragma unroll
        for (int j = 0; j < 2; ++j) {
            int u = tid + j * 256;
            int n = u >> 3, g = u & 7;
            const __half* src = wsrc + (size_t)(fbase + n) * KTOT + g * 8;
            uint32_t dst = bufb + n * 128 + (((g ^ (n & 7))) << 4);
            CP_ASYNC16(dst, src);
        }
    };

    // prologue
    issue_B(0);
    CP_COMMIT();
    load_window(0, 0);

    for (int s = 0; s < NSTG; ++s) {
        int cc = s / 9;
        int tap = s - cc * 9;

        if (s + 1 < NSTG) issue_B(s + 1);
        CP_COMMIT();
        CP_WAIT1();            // B(s) complete locally
        __syncthreads();       // publish B(s) + window/bias STS; compute(s-1) done

        // prefetch next chunk's window into the other winbuf
        if (tap == 8 && cc + 1 < 4) load_window(cc + 1, (cc + 1) & 1);

        uint32_t winb = sbase + WIN0 + (uint32_t)(cc & 1) * 32768;
        uint32_t btap = sbase + BOFF + (uint32_t)(s % 3) * 8192;

        int dy = tap / 3 - 1, dx = tap - (tap / 3) * 3 - 1;
        int doff = dy * 16 + dx;

        uint32_t arow[4], ap7[4];
        #pragma unroll
        for (int j = 0; j < 4; ++j) {
            int P = P0[j] + doff;
            arow[j] = (uint32_t)P * 128;
            ap7[j]  = (uint32_t)(P & 7);
        }
        if (wr == 0)
            compute_tap<4>(acc, winb, btap, arow, ap7, brow, bp7, acgl, bg0);
        else
            compute_tap<3>(acc, winb, btap, arow, ap7, brow, bp7, acgl, bg0);
    }

    // ---- epilogue: bias + relu + store ----
    const float* sb = (const float*)(smem + BIASOF);
    int NTe = (wr == 0) ? 4 : 3;
    #pragma unroll
    for (int j = 0; j < 4; ++j) {
        if (j < NTe) {
            int mt = mtb + j;
            #pragma unroll
            for (int u = 0; u < 2; ++u) {
                #pragma unroll
                for (int hf = 0; hf < 2; ++hf) {
                    int nn = wc * 32 + u * 16 + hf * 8 + (lane & 3) * 2;
                    float bz0 = sb[nn], bz1 = sb[nn + 1];
                    #pragma unroll
                    for (int h2 = 0; h2 < 2; ++h2) {
                        int m = mt * 16 + (lane >> 2) + h2 * 8;
                        if (m < 196) {
                            int py = m / 14, px = m - py * 14;
                            float* o = out + (((size_t)nb * HWD + by * OBS + py) * HWD
                                              + bx * OBS + px) * FOUT + fbase + nn;
                            float2 v;
                            v.x = fmaxf(acc[j][u * 2 + hf][h2 * 2 + 0] + bz0, 0.f);
                            v.y = fmaxf(acc[j][u * 2 + hf][h2 * 2 + 1] + bz1, 0.f);
                            *(float2*)o = v;
                        }
                    }
                }
            }
        }
    }
}

extern "C" void kernel_launch(void* const* d_in, const int* in_sizes, int n_in,
                              void* d_out, int out_size) {
    (void)in_sizes; (void)n_in; (void)out_size;
    const float* in   = (const float*)d_in[0];   // (4,224,224,256)
    const float* mask = (const float*)d_in[1];   // (4,224,224,1)
    const float* wgt  = (const float*)d_in[2];   // (3,3,256,256)
    const float* bias = (const float*)d_in[3];   // (256,)
    float* out = (float*)d_out;

    cudaFuncSetAttribute(conv_mma_kernel,
                         cudaFuncAttributeMaxDynamicSharedMemorySize, SMEM_TOTAL);
    wprep_kernel<<<2304, 256>>>(wgt);
    dim3 grid(4, 1024);   // quarter-major: siblings co-scheduled, share window in L2
    conv_mma_kernel<<<grid, 256, SMEM_TOTAL>>>(in, mask, bias, out);
}

// round 16
// speedup vs baseline: 1.9921x; 1.0014x over previous
#include <cuda_runtime.h>
#include <cuda_fp16.h>
#include <cstdint>
#include <cstddef>

#define HWD  224
#define CIN  256
#define FOUT 256
#define OBS  14
#define KTOT 2304            // 9 taps * 256 c
#define NSTG 36              // 4 chunks * 9 taps; stage = 1 tap * 4 k16-steps

// smem layout (bytes)
#define WIN0   0             // two 16x16x64c fp16 windows (32 KB each)
#define BOFF   65536         // 3 cyclic B buffers, 8 KB each (64f x 128B)
#define BIASOF 90112         // 256 B (64 floats)
#define REDOF  90368         // mask-reduce scratch (64B sums + flag)
#define SMEM_TOTAL 90496

__device__ __align__(16) __half g_W2[256 * KTOT];   // [f][tap*256 + c]

__device__ __forceinline__ uint32_t smem_to_u32(const void* p) {
    uint32_t a;
    asm("{ .reg .u64 t; cvta.to.shared.u64 t, %1; cvt.u32.u64 %0, t; }" : "=r"(a) : "l"(p));
    return a;
}

#define LDSM4(r0, r1, r2, r3, addr) \
    asm volatile("ldmatrix.sync.aligned.m8n8.x4.shared.b16 {%0,%1,%2,%3}, [%4];" \
        : "=r"(r0), "=r"(r1), "=r"(r2), "=r"(r3) : "r"(addr))

#define MMA16816(d, a0, a1, a2, a3, b0, b1) \
    asm volatile("mma.sync.aligned.m16n8k16.row.col.f32.f16.f16.f32 " \
        "{%0,%1,%2,%3}, {%4,%5,%6,%7}, {%8,%9}, {%0,%1,%2,%3};" \
        : "+f"((d)[0]), "+f"((d)[1]), "+f"((d)[2]), "+f"((d)[3]) \
        : "r"(a0), "r"(a1), "r"(a2), "r"(a3), "r"(b0), "r"(b1))

#define CP_ASYNC16(dst, src) \
    asm volatile("cp.async.cg.shared.global [%0], [%1], 16;" \
        :: "r"((uint32_t)(dst)), "l"(src) : "memory")
#define CP_COMMIT() asm volatile("cp.async.commit_group;" ::: "memory")
#define CP_WAIT1()  asm volatile("cp.async.wait_group 1;" ::: "memory")

// ---------------------------------------------------------------------------
// Weight transpose to fp16: g_W2[f][k], k = tap*256 + c
// ---------------------------------------------------------------------------
__global__ void wprep_kernel(const float* __restrict__ wgt) {
    int idx = blockIdx.x * 256 + threadIdx.x;
    int f = idx & 255;
    int k = idx >> 8;
    g_W2[(size_t)f * KTOT + k] = __float2half_rn(wgt[(size_t)k * 256 + f]);
}

// ---------------------------------------------------------------------------
// Pipelined per-tap MMA compute: 4 k16-steps; NT m-tiles (compile-time).
// fp32 accumulators (reverted from f16 chains).
// ---------------------------------------------------------------------------
template<int NT>
__device__ __forceinline__ void compute_tap(
    float acc[4][4][4],
    uint32_t winb, uint32_t btap,
    const uint32_t* __restrict__ arow, const uint32_t* __restrict__ ap7,
    const uint32_t* __restrict__ brow, const uint32_t* __restrict__ bp7,
    int acgl, int bg0)
{
    #pragma unroll
    for (int kk = 0; kk < 4; ++kk) {
        uint32_t bfr[2][4];
        int bcg = 2 * kk + bg0;
        #pragma unroll
        for (int u = 0; u < 2; ++u) {
            uint32_t ba = btap + brow[u] + (uint32_t)(((bcg ^ bp7[u])) << 4);
            LDSM4(bfr[u][0], bfr[u][1], bfr[u][2], bfr[u][3], ba);
        }
        int acg = 2 * kk + acgl;
        uint32_t a0, a1, a2, a3;
        {
            uint32_t aa = winb + arow[0] + (uint32_t)(((acg ^ ap7[0])) << 4);
            LDSM4(a0, a1, a2, a3, aa);
        }
        #pragma unroll
        for (int j = 0; j < NT; ++j) {
            uint32_t n0, n1, n2, n3;
            if (j + 1 < NT) {
                uint32_t aa = winb + arow[j + 1] + (uint32_t)(((acg ^ ap7[j + 1])) << 4);
                LDSM4(n0, n1, n2, n3, aa);
            }
            MMA16816(acc[j][0], a0, a1, a2, a3, bfr[0][0], bfr[0][1]);
            MMA16816(acc[j][1], a0, a1, a2, a3, bfr[0][2], bfr[0][3]);
            MMA16816(acc[j][2], a0, a1, a2, a3, bfr[1][0], bfr[1][1]);
            MMA16816(acc[j][3], a0, a1, a2, a3, bfr[1][2], bfr[1][3]);
            if (j + 1 < NT) { a0 = n0; a1 = n1; a2 = n2; a3 = n3; }
        }
    }
}

// ---------------------------------------------------------------------------
// Conv kernel: per (block, 64-filter quarter), 256 threads / 8 warps,
// 2 CTAs per SM (reg-exact: 256 x 128 x 2 = 64K regs).
// wc = warp&1 (n32), wr = warp>>1 (m-tile bases {0,4,7,10}, sizes {4,3,3,3}).
// blockIdx.x = filter quarter (fast) so sibling CTAs share window via L2.
// ---------------------------------------------------------------------------
__global__ void __launch_bounds__(256, 2)
conv_mma_kernel(const float* __restrict__ in, const float* __restrict__ mask,
                const float* __restrict__ bias, float* __restrict__ out) {
    int fquart = blockIdx.x;          // 0..3
    int b = blockIdx.y;               // 0..1023
    int nb = b >> 8, by = (b >> 4) & 15, bx = b & 15;
    int tid = threadIdx.x;
    int fbase = fquart * 64;

    extern __shared__ char smem[];
    uint32_t sbase = smem_to_u32(smem);

    // ---- activity test (pooled mask mean > 0.5) ----
    {
        double* sred = (double*)(smem + REDOF);
        int* sflag = (int*)(smem + REDOF + 64);
        int ty = tid >> 4, tx = tid & 15;
        int h = by * OBS - 1 + ty;
        int w = bx * OBS - 1 + tx;
        float v = 0.f;
        if ((unsigned)h < HWD && (unsigned)w < HWD)
            v = mask[(nb * HWD + h) * HWD + w];
        double d = (double)v;
        #pragma unroll
        for (int o = 16; o > 0; o >>= 1)
            d += __shfl_down_sync(0xffffffffu, d, o);
        if ((tid & 31) == 0) sred[tid >> 5] = d;
        __syncthreads();
        if (tid == 0) {
            double s = 0.0;
            #pragma unroll
            for (int i = 0; i < 8; ++i) s += sred[i];
            *sflag = (s * (1.0 / 256.0) > 0.5) ? 1 : 0;
        }
        __syncthreads();
        if (!*sflag) {
            if (tid < 196) {
                int Y = by * OBS + tid / OBS, X = bx * OBS + tid % OBS;
                float4* o = (float4*)(out + (((size_t)nb * HWD + Y) * HWD + X) * FOUT + fbase);
                float4 z = make_float4(0.f, 0.f, 0.f, 0.f);
                #pragma unroll
                for (int i = 0; i < 16; ++i) o[i] = z;
            }
            return;
        }
    }

    int warp = tid >> 5, lane = tid & 31;
    int wc = warp & 1;            // n column-group (n32)
    int wr = warp >> 1;           // m row-group 0..3
    int mtb = (wr == 0) ? 0 : (3 * wr + 1);   // 0,4,7,10

    if (tid < 16) ((float4*)(smem + BIASOF))[tid] = ((const float4*)(bias + fbase))[tid];

    // per-lane A-row table (window pixel index per m-tile, pre-halo)
    int P0[4];
    {
        int mrow = (lane & 7) + ((lane >> 3) & 1) * 8;
        #pragma unroll
        for (int j = 0; j < 4; ++j) {
            int mt = mtb + j;
            if (mt > 12) mt = 12;
            int m = mt * 16 + mrow;
            if (m > 195) m = 195;
            int py = m / 14, px = m - py * 14;
            P0[j] = (py + 1) * 16 + (px + 1);
        }
    }
    int acgl = (lane >> 4) & 1;
    int bnl  = ((lane >> 4) & 1) * 8 + (lane & 7);
    int bg0  = (lane >> 3) & 1;

    uint32_t brow[2], bp7[2];
    #pragma unroll
    for (int u = 0; u < 2; ++u) {
        int bn = wc * 32 + u * 16 + bnl;       // < 64
        brow[u] = (uint32_t)bn * 128;
        bp7[u]  = (uint32_t)(bn & 7);
    }

    float acc[4][4][4];
    #pragma unroll
    for (int j = 0; j < 4; ++j)
        #pragma unroll
        for (int t = 0; t < 4; ++t)
            #pragma unroll
            for (int e = 0; e < 4; ++e) acc[j][t][e] = 0.f;

    const float* inb = in + (size_t)nb * HWD * HWD * CIN;
    int h0 = by * OBS - 1;
    int w0 = bx * OBS - 1;

    // window loader: 2048 uint4 units over 256 threads (8 each)
    auto load_window = [&](int cc, int wb) {
        int c0 = cc * 64;
        char* wdst = smem + WIN0 + wb * 32768;
        #pragma unroll
        for (int j = 0; j < 8; ++j) {
            int u = tid + j * 256;
            int p = u >> 3, g = u & 7;
            int y = p >> 4, x = p & 15;
            int gy = h0 + y, gx = w0 + x;
            float v[8];
            #pragma unroll
            for (int e = 0; e < 8; ++e) v[e] = 0.f;
            if ((unsigned)gy < HWD && (unsigned)gx < HWD) {
                const float* sp = inb + (((size_t)gy * HWD + gx) * CIN) + c0 + g * 8;
                float4 va = ((const float4*)sp)[0];
                float4 vb = ((const float4*)sp)[1];
                v[0] = va.x; v[1] = va.y; v[2] = va.z; v[3] = va.w;
                v[4] = vb.x; v[5] = vb.y; v[6] = vb.z; v[7] = vb.w;
            }
            union { __half hf[8]; uint4 u4; } H;
            #pragma unroll
            for (int e = 0; e < 8; ++e) H.hf[e] = __float2half_rn(v[e]);
            *(uint4*)(wdst + p * 128 + (((g ^ (p & 7))) << 4)) = H.u4;
        }
    };

    // B stage issuer: 1 tap = 64 rows x 128B = 512 uint4 over 256 threads
    auto issue_B = [&](int t) {
        int cct = t / 9, tapt = t - cct * 9;
        uint32_t bufb = sbase + BOFF + (uint32_t)(t % 3) * 8192;
        const __half* wsrc = g_W2 + tapt * 256 + cct * 64;
        #pragma unroll
        for (int j = 0; j < 2; ++j) {
            int u = tid + j * 256;
            int n = u >> 3, g = u & 7;
            const __half* src = wsrc + (size_t)(fbase + n) * KTOT + g * 8;
            uint32_t dst = bufb + n * 128 + (((g ^ (n & 7))) << 4);
            CP_ASYNC16(dst, src);
        }
    };

    // prologue
    issue_B(0);
    CP_COMMIT();
    load_window(0, 0);

    for (int s = 0; s < NSTG; ++s) {
        int cc = s / 9;
        int tap = s - cc * 9;

        if (s + 1 < NSTG) issue_B(s + 1);
        CP_COMMIT();
        CP_WAIT1();            // B(s) complete locally
        __syncthreads();       // publish B(s) + window/bias STS; compute(s-1) done

        // prefetch next chunk's window into the other winbuf
        if (tap == 8 && cc + 1 < 4) load_window(cc + 1, (cc + 1) & 1);

        uint32_t winb = sbase + WIN0 + (uint32_t)(cc & 1) * 32768;
        uint32_t btap = sbase + BOFF + (uint32_t)(s % 3) * 8192;

        int dy = tap / 3 - 1, dx = tap - (tap / 3) * 3 - 1;
        int doff = dy * 16 + dx;

        uint32_t arow[4], ap7[4];
        #pragma unroll
        for (int j = 0; j < 4; ++j) {
            int P = P0[j] + doff;
            arow[j] = (uint32_t)P * 128;
            ap7[j]  = (uint32_t)(P & 7);
        }
        if (wr == 0)
            compute_tap<4>(acc, winb, btap, arow, ap7, brow, bp7, acgl, bg0);
        else
            compute_tap<3>(acc, winb, btap, arow, ap7, brow, bp7, acgl, bg0);
    }

    // ---- epilogue: bias + relu + store ----
    const float* sb = (const float*)(smem + BIASOF);
    int NTe = (wr == 0) ? 4 : 3;
    #pragma unroll
    for (int j = 0; j < 4; ++j) {
        if (j < NTe) {
            int mt = mtb + j;
            #pragma unroll
            for (int u = 0; u < 2; ++u) {
                #pragma unroll
                for (int hf = 0; hf < 2; ++hf) {
                    int nn = wc * 32 + u * 16 + hf * 8 + (lane & 3) * 2;
                    float bz0 = sb[nn], bz1 = sb[nn + 1];
                    #pragma unroll
                    for (int h2 = 0; h2 < 2; ++h2) {
                        int m = mt * 16 + (lane >> 2) + h2 * 8;
                        if (m < 196) {
                            int py = m / 14, px = m - py * 14;
                            float* o = out + (((size_t)nb * HWD + by * OBS + py) * HWD
                                              + bx * OBS + px) * FOUT + fbase + nn;
                            float2 v;
                            v.x = fmaxf(acc[j][u * 2 + hf][h2 * 2 + 0] + bz0, 0.f);
                            v.y = fmaxf(acc[j][u * 2 + hf][h2 * 2 + 1] + bz1, 0.f);
                            *(float2*)o = v;
                        }
                    }
                }
            }
        }
    }
}

extern "C" void kernel_launch(void* const* d_in, const int* in_sizes, int n_in,
                              void* d_out, int out_size) {
    (void)in_sizes; (void)n_in; (void)out_size;
    const float* in   = (const float*)d_in[0];   // (4,224,224,256)
    const float* mask = (const float*)d_in[1];   // (4,224,224,1)
    const float* wgt  = (const float*)d_in[2];   // (3,3,256,256)
    const float* bias = (const float*)d_in[3];   // (256,)
    float* out = (float*)d_out;

    cudaFuncSetAttribute(conv_mma_kernel,
                         cudaFuncAttributeMaxDynamicSharedMemorySize, SMEM_TOTAL);
    wprep_kernel<<<2304, 256>>>(wgt);
    dim3 grid(4, 1024);   // quarter-major: siblings co-scheduled, share window in L2
    conv_mma_kernel<<<grid, 256, SMEM_TOTAL>>>(in, mask, bias, out);
}